// round 2
// baseline (speedup 1.0000x reference)
#include <cuda_runtime.h>
#include <cuda_bf16.h>

// Problem constants
#define B 4
#define L 512
#define E 1024
#define H 128
#define NR (B * L)          // 2048 rows per tensor

// Scratch: hidden activations for rec (rows 0..NR-1) and lig (rows NR..2NR-1)
__device__ __align__(16) float g_hid[2 * NR * H];
__device__ unsigned g_maxu[B];

__device__ __forceinline__ float tanh_ap(float x) {
    float y;
    asm("tanh.approx.f32 %0, %1;" : "=f"(y) : "f"(x));
    return y;
}

__device__ __forceinline__ unsigned fenc(float f) {
    unsigned b = __float_as_uint(f);
    return (b & 0x80000000u) ? ~b : (b | 0x80000000u);
}
__device__ __forceinline__ float fdec(unsigned u) {
    return (u & 0x80000000u) ? __uint_as_float(u & 0x7fffffffu)
                             : __uint_as_float(~u);
}

// ---------------------------------------------------------------------------
// Kernel 0: init per-batch max accumulators
// ---------------------------------------------------------------------------
__global__ void init_kernel() {
    if (threadIdx.x < B) g_maxu[threadIdx.x] = 0u;  // below encode of any real
}

// ---------------------------------------------------------------------------
// Kernel 1: hid = relu(emb @ W1 + b1) for rec and lig in one grid.
// M-tile 32, N = 128 (full), K-tile 16. 256 threads, 4x4 micro-tile.
// Grid: 2*NR/32 = 128 blocks.
// ---------------------------------------------------------------------------
__global__ __launch_bounds__(256) void gemm_relu_kernel(
    const float* __restrict__ rec, const float* __restrict__ lig,
    const float* __restrict__ W1, const float* __restrict__ b1)
{
    __shared__ __align__(16) float A_s[32][16];
    __shared__ __align__(16) float W_s[16][128];

    const int t    = threadIdx.x;
    const int tcol = t & 31;   // float4 column group (0..31) -> cols 4*tcol..+3
    const int trow = t >> 5;   // row group (0..7) -> rows 4*trow..+3
    const int row0 = blockIdx.x * 32;

    float acc[4][4];
#pragma unroll
    for (int u = 0; u < 4; ++u)
#pragma unroll
        for (int v = 0; v < 4; ++v) acc[u][v] = 0.f;

    for (int k0 = 0; k0 < E; k0 += 16) {
        if (t < 128) {
            int ar = t >> 2, ac = (t & 3) * 4;
            int gr = row0 + ar;
            const float* p = (gr < NR) ? (rec + (size_t)gr * E)
                                       : (lig + (size_t)(gr - NR) * E);
            float4 v = *(const float4*)(p + k0 + ac);
            *(float4*)&A_s[ar][ac] = v;
        }
        {
            const float4* wsrc = (const float4*)(W1 + (size_t)k0 * H);
            float4* wdst = (float4*)&W_s[0][0];
            wdst[t]       = wsrc[t];
            wdst[t + 256] = wsrc[t + 256];
        }
        __syncthreads();
#pragma unroll
        for (int kk = 0; kk < 16; ++kk) {
            float4 wv = *(const float4*)&W_s[kk][tcol * 4];
#pragma unroll
            for (int u = 0; u < 4; ++u) {
                float a = A_s[trow * 4 + u][kk];
                acc[u][0] = fmaf(a, wv.x, acc[u][0]);
                acc[u][1] = fmaf(a, wv.y, acc[u][1]);
                acc[u][2] = fmaf(a, wv.z, acc[u][2]);
                acc[u][3] = fmaf(a, wv.w, acc[u][3]);
            }
        }
        __syncthreads();
    }

    float4 bv = ((const float4*)b1)[tcol];
#pragma unroll
    for (int u = 0; u < 4; ++u) {
        int gr = row0 + trow * 4 + u;
        float4 o;
        o.x = fmaxf(acc[u][0] + bv.x, 0.f);
        o.y = fmaxf(acc[u][1] + bv.y, 0.f);
        o.z = fmaxf(acc[u][2] + bv.z, 0.f);
        o.w = fmaxf(acc[u][3] + bv.w, 0.f);
        *(float4*)&g_hid[(size_t)gr * H + tcol * 4] = o;
    }
}

// ---------------------------------------------------------------------------
// Kernel 2: per (i,j) tile, compute S_k(i,j) = sum_h tanh(r_i[h]*l_j[h])*w_k[h]
// for a 32x32 S-tile (rows i0-1..i0+30, cols j0-1..j0+30), then combine into a
// 31x31 y-tile, reduce max, atomicMax per batch.
// y(p,q) = cb + S00(p-1,q-1) + S01(p-1,q) + S10(p,q-1) + S11(p,q);
// the maxpool(2,2,floor) + global max over the 513x513 conv output equals the
// max over p,q in [0,512) of y, so we never materialize mat/y.
// ---------------------------------------------------------------------------
#define TS 31       // y-tile size per block
#define LPAD 132    // padded row stride in floats (conflict-free float4)

__global__ __launch_bounds__(1024) void tile_max_kernel(
    const float* __restrict__ conv_w, const float* __restrict__ conv_b)
{
    __shared__ __align__(16) float r_s[32][LPAD];
    __shared__ __align__(16) float l_s[32][LPAD];
    __shared__ float4 w4_s[H];

    const int tx = threadIdx.x;          // j within tile
    const int ty = threadIdx.y;          // i within tile
    const int t  = ty * 32 + tx;
    const int b  = blockIdx.z;
    const int i0 = blockIdx.y * TS;      // first y-row p of this block
    const int j0 = blockIdx.x * TS;      // first y-col q

    // Load r rows i = i0-1+ty, l rows j = j0-1+ty (row = ty for loading).
    {
        int iload = i0 - 1 + ty;
        int jload = j0 - 1 + ty;
        float4 zz = make_float4(0.f, 0.f, 0.f, 0.f);
        float4 rv = zz, lv = zz;
        if (iload >= 0 && iload < L)
            rv = ((const float4*)(g_hid + (size_t)(b * L + iload) * H))[tx];
        if (jload >= 0 && jload < L)
            lv = ((const float4*)(g_hid + (size_t)(NR + b * L + jload) * H))[tx];
        ((float4*)&r_s[ty][0])[tx] = rv;
        ((float4*)&l_s[ty][0])[tx] = lv;
        if (t < H) w4_s[t] = ((const float4*)conv_w)[t];  // (w00,w01,w10,w11)
    }
    __syncthreads();

    float s0 = 0.f, s1 = 0.f, s2 = 0.f, s3 = 0.f;
    const float4* rp = (const float4*)&r_s[ty][0];
    const float4* lp = (const float4*)&l_s[tx][0];
#pragma unroll 8
    for (int h4 = 0; h4 < H / 4; ++h4) {
        float4 rv = rp[h4];
        float4 lv = lp[h4];
        float t0 = tanh_ap(rv.x * lv.x);
        float t1 = tanh_ap(rv.y * lv.y);
        float t2 = tanh_ap(rv.z * lv.z);
        float t3 = tanh_ap(rv.w * lv.w);
        float4 w0 = w4_s[4 * h4 + 0];
        float4 w1 = w4_s[4 * h4 + 1];
        float4 w2 = w4_s[4 * h4 + 2];
        float4 w3 = w4_s[4 * h4 + 3];
        s0 = fmaf(t0, w0.x, s0); s1 = fmaf(t0, w0.y, s1);
        s2 = fmaf(t0, w0.z, s2); s3 = fmaf(t0, w0.w, s3);
        s0 = fmaf(t1, w1.x, s0); s1 = fmaf(t1, w1.y, s1);
        s2 = fmaf(t1, w1.z, s2); s3 = fmaf(t1, w1.w, s3);
        s0 = fmaf(t2, w2.x, s0); s1 = fmaf(t2, w2.y, s1);
        s2 = fmaf(t2, w2.z, s2); s3 = fmaf(t2, w2.w, s3);
        s0 = fmaf(t3, w3.x, s0); s1 = fmaf(t3, w3.y, s1);
        s2 = fmaf(t3, w3.z, s2); s3 = fmaf(t3, w3.w, s3);
    }
    __syncthreads();  // everyone done reading r_s/l_s

    // S tile aliases r_s storage: 32 x 33 float4 = 16896 B = sizeof(r_s)
    float4* S = (float4*)&r_s[0][0];
    S[ty * 33 + tx] = make_float4(s0, s1, s2, s3);
    __syncthreads();

    float m = -3.4e38f;
    if (tx < TS && ty < TS) {
        int p = i0 + ty, q = j0 + tx;
        if (p < L && q < L) {
            float4 a  = S[ty * 33 + tx];             // S00(p-1,q-1)
            float4 bq = S[ty * 33 + tx + 1];         // S01(p-1,q)
            float4 c  = S[(ty + 1) * 33 + tx];       // S10(p,q-1)
            float4 d  = S[(ty + 1) * 33 + tx + 1];   // S11(p,q)
            m = conv_b[0] + a.x + bq.y + c.z + d.w;
        }
    }

    // block max reduce (scratch aliases l_s, free after the h-loop sync)
#pragma unroll
    for (int o = 16; o > 0; o >>= 1)
        m = fmaxf(m, __shfl_xor_sync(0xffffffffu, m, o));
    float* red = &l_s[0][0];
    if (tx == 0) red[ty] = m;
    __syncthreads();
    if (ty == 0) {
        float v = red[tx];
#pragma unroll
        for (int o = 16; o > 0; o >>= 1)
            v = fmaxf(v, __shfl_xor_sync(0xffffffffu, v, o));
        if (tx == 0) atomicMax(&g_maxu[b], fenc(v));
    }
}

// ---------------------------------------------------------------------------
// Kernel 3: sigmoid(max) -> out
// ---------------------------------------------------------------------------
__global__ void finalize_kernel(float* __restrict__ out) {
    int i = threadIdx.x;
    if (i < B) {
        float m = fdec(g_maxu[i]);
        out[i] = 1.f / (1.f + expf(-m));
    }
}

// ---------------------------------------------------------------------------
extern "C" void kernel_launch(void* const* d_in, const int* in_sizes, int n_in,
                              void* d_out, int out_size)
{
    // Bind by size where unambiguous; rec/lig are the two equal-size large
    // arrays, taken in metadata order.
    const float *rec = 0, *lig = 0, *W1 = 0, *b1 = 0, *conv_w = 0, *conv_b = 0;
    for (int i = 0; i < n_in; ++i) {
        int n = in_sizes[i];
        const float* p = (const float*)d_in[i];
        if (n == B * L * E)      { if (!rec) rec = p; else lig = p; }
        else if (n == E * H)     W1 = p;
        else if (n == H)         b1 = p;
        else if (n == H * 4)     conv_w = p;
        else if (n == 1)         conv_b = p;
    }
    float* out = (float*)d_out;

    init_kernel<<<1, 32>>>();
    gemm_relu_kernel<<<2 * NR / 32, 256>>>(rec, lig, W1, b1);
    dim3 g2((L + TS - 1) / TS, (L + TS - 1) / TS, B);  // 17 x 17 x 4
    tile_max_kernel<<<g2, dim3(32, 32)>>>(conv_w, conv_b);
    finalize_kernel<<<1, 32>>>(out);
}